// round 5
// baseline (speedup 1.0000x reference)
#include <cuda_runtime.h>
#include <cstddef>
#include <cstdint>

#define NN 100000
#define IN_DIM 256
#define H_DIM 128
#define C_DIM 40

// Scratch (device globals — no allocation allowed)
__device__ float g_h2[(size_t)NN * C_DIM];   // (relu(X@W1))@W2
__device__ float g_z1[(size_t)NN * C_DIM];   // first propagation
__device__ int   g_rowptr[NN + 1];           // CSR offsets from sorted edge_dst

// ---------------------------------------------------------------------------
// tf32 helpers
// ---------------------------------------------------------------------------
__device__ __forceinline__ float tf32r(float x) {
    uint32_t u;
    asm("cvt.rna.tf32.f32 %0, %1;" : "=r"(u) : "f"(x));
    return __uint_as_float(u);
}

__device__ __forceinline__ void mma_tf32(float* c, const uint32_t* a,
                                         uint32_t b0, uint32_t b1) {
    asm volatile(
        "mma.sync.aligned.m16n8k8.row.col.f32.tf32.tf32.f32 "
        "{%0,%1,%2,%3}, {%4,%5,%6,%7}, {%8,%9}, {%0,%1,%2,%3};\n"
        : "+f"(c[0]), "+f"(c[1]), "+f"(c[2]), "+f"(c[3])
        : "r"(a[0]), "r"(a[1]), "r"(a[2]), "r"(a[3]), "r"(b0), "r"(b1));
}

// ---------------------------------------------------------------------------
// Fused MLP: g_h2 = relu(X[M,256] @ W1[256,128]) @ W2[128,40]
// (unchanged from round 4)
// ---------------------------------------------------------------------------
#define S1_AS_STRIDE 36
#define S1_BS_STRIDE 132
#define S2_H_STRIDE 132
#define S2_W_STRIDE 44
#define FUSED_SMEM_BYTES 90112

extern __shared__ float sm[];

__global__ __launch_bounds__(256) void fused_mlp_kernel(
    const float* __restrict__ A, const float* __restrict__ W1,
    const float* __restrict__ W2, int M) {
    const int tid = threadIdx.x;
    const int lane = tid & 31;
    const int wid = tid >> 5;
    const int blockRow = blockIdx.x;

    float* As = sm;                           // [2][128][36]
    float* Bs = sm + 2 * 128 * S1_AS_STRIDE;  // [2][32][132]

    const int warp_m = wid >> 1;   // 0..3 -> 32 rows each
    const int warp_n = wid & 1;    // 0..1 -> 64 cols each

    float acc[2][8][4];
    #pragma unroll
    for (int mi = 0; mi < 2; mi++)
        #pragma unroll
        for (int ni = 0; ni < 8; ni++)
            #pragma unroll
            for (int q = 0; q < 4; q++) acc[mi][ni][q] = 0.f;

    // ---- prologue: k-tile 0 -> buffer 0 ----
    {
        #pragma unroll
        for (int t = 0; t < 4; t++) {
            const int f4 = tid + t * 256;
            const int row = f4 >> 3, kc = (f4 & 7) * 4;
            float4 a4 = make_float4(0.f, 0.f, 0.f, 0.f);
            const int arow = blockRow * 128 + row;
            if (arow < M)
                a4 = *reinterpret_cast<const float4*>(A + (size_t)arow * IN_DIM + kc);
            float* p = As + row * S1_AS_STRIDE + kc;
            p[0] = tf32r(a4.x); p[1] = tf32r(a4.y);
            p[2] = tf32r(a4.z); p[3] = tf32r(a4.w);
            const int bk = f4 >> 5, nc = (f4 & 31) * 4;
            float4 b4 = *reinterpret_cast<const float4*>(W1 + (size_t)bk * H_DIM + nc);
            float* q = Bs + bk * S1_BS_STRIDE + nc;
            q[0] = tf32r(b4.x); q[1] = tf32r(b4.y);
            q[2] = tf32r(b4.z); q[3] = tf32r(b4.w);
        }
    }
    __syncthreads();

    int cur = 0;
    constexpr int NKT = IN_DIM / 32;  // 8
    for (int kt = 0; kt < NKT; kt++) {
        float4 a_pref[4], b_pref[4];
        if (kt < NKT - 1) {
            const int k0 = (kt + 1) * 32;
            #pragma unroll
            for (int t = 0; t < 4; t++) {
                const int f4 = tid + t * 256;
                const int row = f4 >> 3, kc = (f4 & 7) * 4;
                const int arow = blockRow * 128 + row;
                a_pref[t] = make_float4(0.f, 0.f, 0.f, 0.f);
                if (arow < M)
                    a_pref[t] = *reinterpret_cast<const float4*>(
                        A + (size_t)arow * IN_DIM + k0 + kc);
                const int bk = f4 >> 5, nc = (f4 & 31) * 4;
                b_pref[t] = *reinterpret_cast<const float4*>(
                    W1 + (size_t)(k0 + bk) * H_DIM + nc);
            }
        }

        const float* Ac = As + cur * 128 * S1_AS_STRIDE;
        const float* Bc = Bs + cur * 32 * S1_BS_STRIDE;
        #pragma unroll
        for (int k8 = 0; k8 < 4; k8++) {
            const int kk = k8 * 8;
            uint32_t af[2][4];
            #pragma unroll
            for (int mi = 0; mi < 2; mi++) {
                const int rb = warp_m * 32 + mi * 16 + (lane >> 2);
                const int kc = kk + (lane & 3);
                af[mi][0] = __float_as_uint(Ac[rb * S1_AS_STRIDE + kc]);
                af[mi][1] = __float_as_uint(Ac[(rb + 8) * S1_AS_STRIDE + kc]);
                af[mi][2] = __float_as_uint(Ac[rb * S1_AS_STRIDE + kc + 4]);
                af[mi][3] = __float_as_uint(Ac[(rb + 8) * S1_AS_STRIDE + kc + 4]);
            }
            #pragma unroll
            for (int ni = 0; ni < 8; ni++) {
                const int nb = warp_n * 64 + ni * 8 + (lane >> 2);
                const uint32_t b0 =
                    __float_as_uint(Bc[(kk + (lane & 3)) * S1_BS_STRIDE + nb]);
                const uint32_t b1 =
                    __float_as_uint(Bc[(kk + 4 + (lane & 3)) * S1_BS_STRIDE + nb]);
                mma_tf32(acc[0][ni], af[0], b0, b1);
                mma_tf32(acc[1][ni], af[1], b0, b1);
            }
        }

        if (kt < NKT - 1) {
            const int nxt = 1 - cur;
            float* An = As + nxt * 128 * S1_AS_STRIDE;
            float* Bn = Bs + nxt * 32 * S1_BS_STRIDE;
            #pragma unroll
            for (int t = 0; t < 4; t++) {
                const int f4 = tid + t * 256;
                const int row = f4 >> 3, kc = (f4 & 7) * 4;
                float* p = An + row * S1_AS_STRIDE + kc;
                p[0] = tf32r(a_pref[t].x); p[1] = tf32r(a_pref[t].y);
                p[2] = tf32r(a_pref[t].z); p[3] = tf32r(a_pref[t].w);
                const int bk = f4 >> 5, nc = (f4 & 31) * 4;
                float* q = Bn + bk * S1_BS_STRIDE + nc;
                q[0] = tf32r(b_pref[t].x); q[1] = tf32r(b_pref[t].y);
                q[2] = tf32r(b_pref[t].z); q[3] = tf32r(b_pref[t].w);
            }
            __syncthreads();
            cur = nxt;
        }
    }

    // ---- stage 1 -> stage 2 transition ----
    __syncthreads();

    float* H  = sm;                      // [128][132]
    float* Ws = sm + 128 * S2_H_STRIDE;  // [128][44]

    #pragma unroll
    for (int mi = 0; mi < 2; mi++) {
        const int r0 = warp_m * 32 + mi * 16 + (lane >> 2);
        #pragma unroll
        for (int ni = 0; ni < 8; ni++) {
            const int c0 = warp_n * 64 + ni * 8 + 2 * (lane & 3);
            H[r0 * S2_H_STRIDE + c0]           = tf32r(fmaxf(acc[mi][ni][0], 0.f));
            H[r0 * S2_H_STRIDE + c0 + 1]       = tf32r(fmaxf(acc[mi][ni][1], 0.f));
            H[(r0 + 8) * S2_H_STRIDE + c0]     = tf32r(fmaxf(acc[mi][ni][2], 0.f));
            H[(r0 + 8) * S2_H_STRIDE + c0 + 1] = tf32r(fmaxf(acc[mi][ni][3], 0.f));
        }
    }
    for (int i = tid; i < H_DIM * C_DIM; i += 256)
        Ws[(i / C_DIM) * S2_W_STRIDE + (i % C_DIM)] = tf32r(W2[i]);
    __syncthreads();

    const int rb2 = wid * 16;
    float acc2[5][4];
    #pragma unroll
    for (int ni = 0; ni < 5; ni++)
        #pragma unroll
        for (int q = 0; q < 4; q++) acc2[ni][q] = 0.f;

    #pragma unroll
    for (int k8 = 0; k8 < 16; k8++) {
        const int kk = k8 * 8;
        uint32_t af[4];
        const int rr = rb2 + (lane >> 2);
        const int kc = kk + (lane & 3);
        af[0] = __float_as_uint(H[rr * S2_H_STRIDE + kc]);
        af[1] = __float_as_uint(H[(rr + 8) * S2_H_STRIDE + kc]);
        af[2] = __float_as_uint(H[rr * S2_H_STRIDE + kc + 4]);
        af[3] = __float_as_uint(H[(rr + 8) * S2_H_STRIDE + kc + 4]);
        #pragma unroll
        for (int ni = 0; ni < 5; ni++) {
            const int nb = ni * 8 + (lane >> 2);
            const uint32_t b0 =
                __float_as_uint(Ws[(kk + (lane & 3)) * S2_W_STRIDE + nb]);
            const uint32_t b1 =
                __float_as_uint(Ws[(kk + 4 + (lane & 3)) * S2_W_STRIDE + nb]);
            mma_tf32(acc2[ni], af, b0, b1);
        }
    }

    const int row0 = blockRow * 128 + rb2 + (lane >> 2);
    #pragma unroll
    for (int ni = 0; ni < 5; ni++) {
        const int c0 = ni * 8 + 2 * (lane & 3);
        if (row0 < M) {
            float2 v = make_float2(acc2[ni][0], acc2[ni][1]);
            *reinterpret_cast<float2*>(g_h2 + (size_t)row0 * C_DIM + c0) = v;
        }
        if (row0 + 8 < M) {
            float2 v = make_float2(acc2[ni][2], acc2[ni][3]);
            *reinterpret_cast<float2*>(g_h2 + (size_t)(row0 + 8) * C_DIM + c0) = v;
        }
    }
}

// ---------------------------------------------------------------------------
// Row-pointer build: edge_dst is SORTED. rowptr[v] = lower_bound(dst, v).
// ---------------------------------------------------------------------------
__global__ void rowptr_kernel(const int* __restrict__ dst, int N, int E) {
    const int v = blockIdx.x * blockDim.x + threadIdx.x;
    if (v > N) return;
    int lo = 0, hi = E;
    while (lo < hi) {
        const int mid = (lo + hi) >> 1;
        if (__ldg(dst + mid) < v) lo = mid + 1; else hi = mid;
    }
    g_rowptr[v] = lo;
}

// ---------------------------------------------------------------------------
// CSR SPMM: out[v] = sum_{i in [rowptr[v], rowptr[v+1])} val[i] * x[src[i]]
// 320 threads = 64 groups x 5 lanes; group owns one node; lane owns 8 cols
// (two float4s). 4-edge unroll -> 8 outstanding LDG.128 per thread.
// No atomics, no output zeroing.
// ---------------------------------------------------------------------------
__device__ __forceinline__ void fma4(float4& a, float v, const float4& x) {
    a.x = fmaf(v, x.x, a.x); a.y = fmaf(v, x.y, a.y);
    a.z = fmaf(v, x.z, a.z); a.w = fmaf(v, x.w, a.w);
}

__global__ __launch_bounds__(320) void spmm_csr_kernel(
    const int* __restrict__ src, const float* __restrict__ val,
    const float* __restrict__ x, float* __restrict__ out, int N) {
    const int tid = threadIdx.x;
    const int node = blockIdx.x * 64 + tid / 5;
    const int lane = tid % 5;
    if (node >= N) return;

    const int start = __ldg(g_rowptr + node);
    const int end   = __ldg(g_rowptr + node + 1);
    const float* xb = x + (size_t)lane * 8;

    float4 aA0 = make_float4(0.f, 0.f, 0.f, 0.f);
    float4 aB0 = make_float4(0.f, 0.f, 0.f, 0.f);
    float4 aA1 = make_float4(0.f, 0.f, 0.f, 0.f);
    float4 aB1 = make_float4(0.f, 0.f, 0.f, 0.f);

    int i = start;
    for (; i + 4 <= end; i += 4) {
        const int   s0 = __ldg(src + i);
        const int   s1 = __ldg(src + i + 1);
        const int   s2 = __ldg(src + i + 2);
        const int   s3 = __ldg(src + i + 3);
        const float v0 = __ldg(val + i);
        const float v1 = __ldg(val + i + 1);
        const float v2 = __ldg(val + i + 2);
        const float v3 = __ldg(val + i + 3);
        const float4* p0 = reinterpret_cast<const float4*>(xb + (size_t)s0 * C_DIM);
        const float4* p1 = reinterpret_cast<const float4*>(xb + (size_t)s1 * C_DIM);
        const float4* p2 = reinterpret_cast<const float4*>(xb + (size_t)s2 * C_DIM);
        const float4* p3 = reinterpret_cast<const float4*>(xb + (size_t)s3 * C_DIM);
        const float4 x0a = p0[0], x0b = p0[1];
        const float4 x1a = p1[0], x1b = p1[1];
        const float4 x2a = p2[0], x2b = p2[1];
        const float4 x3a = p3[0], x3b = p3[1];
        fma4(aA0, v0, x0a); fma4(aB0, v0, x0b);
        fma4(aA1, v1, x1a); fma4(aB1, v1, x1b);
        fma4(aA0, v2, x2a); fma4(aB0, v2, x2b);
        fma4(aA1, v3, x3a); fma4(aB1, v3, x3b);
    }
    if (i + 2 <= end) {
        const int   s0 = __ldg(src + i);
        const int   s1 = __ldg(src + i + 1);
        const float v0 = __ldg(val + i);
        const float v1 = __ldg(val + i + 1);
        const float4* p0 = reinterpret_cast<const float4*>(xb + (size_t)s0 * C_DIM);
        const float4* p1 = reinterpret_cast<const float4*>(xb + (size_t)s1 * C_DIM);
        const float4 x0a = p0[0], x0b = p0[1];
        const float4 x1a = p1[0], x1b = p1[1];
        fma4(aA0, v0, x0a); fma4(aB0, v0, x0b);
        fma4(aA1, v1, x1a); fma4(aB1, v1, x1b);
        i += 2;
    }
    if (i < end) {
        const int   s0 = __ldg(src + i);
        const float v0 = __ldg(val + i);
        const float4* p0 = reinterpret_cast<const float4*>(xb + (size_t)s0 * C_DIM);
        fma4(aA0, v0, p0[0]); fma4(aB0, v0, p0[1]);
    }

    float4 rA, rB;
    rA.x = aA0.x + aA1.x; rA.y = aA0.y + aA1.y;
    rA.z = aA0.z + aA1.z; rA.w = aA0.w + aA1.w;
    rB.x = aB0.x + aB1.x; rB.y = aB0.y + aB1.y;
    rB.z = aB0.z + aB1.z; rB.w = aB0.w + aB1.w;
    float* ob = out + (size_t)node * C_DIM + lane * 8;
    *reinterpret_cast<float4*>(ob)     = rA;
    *reinterpret_cast<float4*>(ob + 4) = rB;
}

extern "C" void kernel_launch(void* const* d_in, const int* in_sizes, int n_in,
                              void* d_out, int out_size) {
    const float* features = (const float*)d_in[0];
    const float* W1       = (const float*)d_in[1];
    const float* W2       = (const float*)d_in[2];
    const int*   edge_src = (const int*)d_in[3];
    const int*   edge_dst = (const int*)d_in[4];
    const float* edge_val = (const float*)d_in[5];
    float* out = (float*)d_out;

    const int M = in_sizes[0] / IN_DIM;   // 100000
    const int E = in_sizes[3];            // 1600000

    float *p_h2, *p_z1;
    cudaGetSymbolAddress((void**)&p_h2, g_h2);
    cudaGetSymbolAddress((void**)&p_z1, g_z1);

    static bool attr_set = false;
    if (!attr_set) {
        cudaFuncSetAttribute(fused_mlp_kernel,
                             cudaFuncAttributeMaxDynamicSharedMemorySize,
                             FUSED_SMEM_BYTES);
        attr_set = true;
    }

    // 1) h2 = relu(X @ W1) @ W2  (single fused kernel)
    fused_mlp_kernel<<<(M + 127) / 128, 256, FUSED_SMEM_BYTES>>>(
        features, W1, W2, M);

    // 2) CSR row pointers from sorted edge_dst (shared by both propagations)
    rowptr_kernel<<<(M + 257) / 256, 256>>>(edge_dst, M, E);

    // 3) z1 = A @ h2 ; out = A @ z1   (no zeroing, no atomics)
    spmm_csr_kernel<<<(M + 63) / 64, 320>>>(edge_src, edge_val, p_h2, p_z1, M);
    spmm_csr_kernel<<<(M + 63) / 64, 320>>>(edge_src, edge_val, p_z1, out, M);
}

// round 6
// speedup vs baseline: 1.0200x; 1.0200x over previous
#include <cuda_runtime.h>
#include <cstddef>
#include <cstdint>

#define NN 100000
#define IN_DIM 256
#define H_DIM 128
#define C_DIM 40

// Scratch (device globals — no allocation allowed)
__device__ float g_h2[(size_t)NN * C_DIM];   // (relu(X@W1))@W2
__device__ float g_z1[(size_t)NN * C_DIM];   // first propagation
__device__ int   g_rowptr[NN + 1];           // CSR offsets from sorted edge_dst

// ---------------------------------------------------------------------------
// tf32 helpers
// ---------------------------------------------------------------------------
__device__ __forceinline__ float tf32r(float x) {
    uint32_t u;
    asm("cvt.rna.tf32.f32 %0, %1;" : "=r"(u) : "f"(x));
    return __uint_as_float(u);
}

__device__ __forceinline__ void mma_tf32(float* c, const uint32_t* a,
                                         uint32_t b0, uint32_t b1) {
    asm volatile(
        "mma.sync.aligned.m16n8k8.row.col.f32.tf32.tf32.f32 "
        "{%0,%1,%2,%3}, {%4,%5,%6,%7}, {%8,%9}, {%0,%1,%2,%3};\n"
        : "+f"(c[0]), "+f"(c[1]), "+f"(c[2]), "+f"(c[3])
        : "r"(a[0]), "r"(a[1]), "r"(a[2]), "r"(a[3]), "r"(b0), "r"(b1));
}

// ---------------------------------------------------------------------------
// Fused MLP: g_h2 = relu(X[M,256] @ W1[256,128]) @ W2[128,40]
// (unchanged from round 4)
// ---------------------------------------------------------------------------
#define S1_AS_STRIDE 36
#define S1_BS_STRIDE 132
#define S2_H_STRIDE 132
#define S2_W_STRIDE 44
#define FUSED_SMEM_BYTES 90112

extern __shared__ float sm[];

__global__ __launch_bounds__(256) void fused_mlp_kernel(
    const float* __restrict__ A, const float* __restrict__ W1,
    const float* __restrict__ W2, int M) {
    const int tid = threadIdx.x;
    const int lane = tid & 31;
    const int wid = tid >> 5;
    const int blockRow = blockIdx.x;

    float* As = sm;                           // [2][128][36]
    float* Bs = sm + 2 * 128 * S1_AS_STRIDE;  // [2][32][132]

    const int warp_m = wid >> 1;   // 0..3 -> 32 rows each
    const int warp_n = wid & 1;    // 0..1 -> 64 cols each

    float acc[2][8][4];
    #pragma unroll
    for (int mi = 0; mi < 2; mi++)
        #pragma unroll
        for (int ni = 0; ni < 8; ni++)
            #pragma unroll
            for (int q = 0; q < 4; q++) acc[mi][ni][q] = 0.f;

    // ---- prologue: k-tile 0 -> buffer 0 ----
    {
        #pragma unroll
        for (int t = 0; t < 4; t++) {
            const int f4 = tid + t * 256;
            const int row = f4 >> 3, kc = (f4 & 7) * 4;
            float4 a4 = make_float4(0.f, 0.f, 0.f, 0.f);
            const int arow = blockRow * 128 + row;
            if (arow < M)
                a4 = *reinterpret_cast<const float4*>(A + (size_t)arow * IN_DIM + kc);
            float* p = As + row * S1_AS_STRIDE + kc;
            p[0] = tf32r(a4.x); p[1] = tf32r(a4.y);
            p[2] = tf32r(a4.z); p[3] = tf32r(a4.w);
            const int bk = f4 >> 5, nc = (f4 & 31) * 4;
            float4 b4 = *reinterpret_cast<const float4*>(W1 + (size_t)bk * H_DIM + nc);
            float* q = Bs + bk * S1_BS_STRIDE + nc;
            q[0] = tf32r(b4.x); q[1] = tf32r(b4.y);
            q[2] = tf32r(b4.z); q[3] = tf32r(b4.w);
        }
    }
    __syncthreads();

    int cur = 0;
    constexpr int NKT = IN_DIM / 32;  // 8
    for (int kt = 0; kt < NKT; kt++) {
        float4 a_pref[4], b_pref[4];
        if (kt < NKT - 1) {
            const int k0 = (kt + 1) * 32;
            #pragma unroll
            for (int t = 0; t < 4; t++) {
                const int f4 = tid + t * 256;
                const int row = f4 >> 3, kc = (f4 & 7) * 4;
                const int arow = blockRow * 128 + row;
                a_pref[t] = make_float4(0.f, 0.f, 0.f, 0.f);
                if (arow < M)
                    a_pref[t] = *reinterpret_cast<const float4*>(
                        A + (size_t)arow * IN_DIM + k0 + kc);
                const int bk = f4 >> 5, nc = (f4 & 31) * 4;
                b_pref[t] = *reinterpret_cast<const float4*>(
                    W1 + (size_t)(k0 + bk) * H_DIM + nc);
            }
        }

        const float* Ac = As + cur * 128 * S1_AS_STRIDE;
        const float* Bc = Bs + cur * 32 * S1_BS_STRIDE;
        #pragma unroll
        for (int k8 = 0; k8 < 4; k8++) {
            const int kk = k8 * 8;
            uint32_t af[2][4];
            #pragma unroll
            for (int mi = 0; mi < 2; mi++) {
                const int rb = warp_m * 32 + mi * 16 + (lane >> 2);
                const int kc = kk + (lane & 3);
                af[mi][0] = __float_as_uint(Ac[rb * S1_AS_STRIDE + kc]);
                af[mi][1] = __float_as_uint(Ac[(rb + 8) * S1_AS_STRIDE + kc]);
                af[mi][2] = __float_as_uint(Ac[rb * S1_AS_STRIDE + kc + 4]);
                af[mi][3] = __float_as_uint(Ac[(rb + 8) * S1_AS_STRIDE + kc + 4]);
            }
            #pragma unroll
            for (int ni = 0; ni < 8; ni++) {
                const int nb = warp_n * 64 + ni * 8 + (lane >> 2);
                const uint32_t b0 =
                    __float_as_uint(Bc[(kk + (lane & 3)) * S1_BS_STRIDE + nb]);
                const uint32_t b1 =
                    __float_as_uint(Bc[(kk + 4 + (lane & 3)) * S1_BS_STRIDE + nb]);
                mma_tf32(acc[0][ni], af[0], b0, b1);
                mma_tf32(acc[1][ni], af[1], b0, b1);
            }
        }

        if (kt < NKT - 1) {
            const int nxt = 1 - cur;
            float* An = As + nxt * 128 * S1_AS_STRIDE;
            float* Bn = Bs + nxt * 32 * S1_BS_STRIDE;
            #pragma unroll
            for (int t = 0; t < 4; t++) {
                const int f4 = tid + t * 256;
                const int row = f4 >> 3, kc = (f4 & 7) * 4;
                float* p = An + row * S1_AS_STRIDE + kc;
                p[0] = tf32r(a_pref[t].x); p[1] = tf32r(a_pref[t].y);
                p[2] = tf32r(a_pref[t].z); p[3] = tf32r(a_pref[t].w);
                const int bk = f4 >> 5, nc = (f4 & 31) * 4;
                float* q = Bn + bk * S1_BS_STRIDE + nc;
                q[0] = tf32r(b_pref[t].x); q[1] = tf32r(b_pref[t].y);
                q[2] = tf32r(b_pref[t].z); q[3] = tf32r(b_pref[t].w);
            }
            __syncthreads();
            cur = nxt;
        }
    }

    // ---- stage 1 -> stage 2 transition ----
    __syncthreads();

    float* H  = sm;                      // [128][132]
    float* Ws = sm + 128 * S2_H_STRIDE;  // [128][44]

    #pragma unroll
    for (int mi = 0; mi < 2; mi++) {
        const int r0 = warp_m * 32 + mi * 16 + (lane >> 2);
        #pragma unroll
        for (int ni = 0; ni < 8; ni++) {
            const int c0 = warp_n * 64 + ni * 8 + 2 * (lane & 3);
            H[r0 * S2_H_STRIDE + c0]           = tf32r(fmaxf(acc[mi][ni][0], 0.f));
            H[r0 * S2_H_STRIDE + c0 + 1]       = tf32r(fmaxf(acc[mi][ni][1], 0.f));
            H[(r0 + 8) * S2_H_STRIDE + c0]     = tf32r(fmaxf(acc[mi][ni][2], 0.f));
            H[(r0 + 8) * S2_H_STRIDE + c0 + 1] = tf32r(fmaxf(acc[mi][ni][3], 0.f));
        }
    }
    for (int i = tid; i < H_DIM * C_DIM; i += 256)
        Ws[(i / C_DIM) * S2_W_STRIDE + (i % C_DIM)] = tf32r(W2[i]);
    __syncthreads();

    const int rb2 = wid * 16;
    float acc2[5][4];
    #pragma unroll
    for (int ni = 0; ni < 5; ni++)
        #pragma unroll
        for (int q = 0; q < 4; q++) acc2[ni][q] = 0.f;

    #pragma unroll
    for (int k8 = 0; k8 < 16; k8++) {
        const int kk = k8 * 8;
        uint32_t af[4];
        const int rr = rb2 + (lane >> 2);
        const int kc = kk + (lane & 3);
        af[0] = __float_as_uint(H[rr * S2_H_STRIDE + kc]);
        af[1] = __float_as_uint(H[(rr + 8) * S2_H_STRIDE + kc]);
        af[2] = __float_as_uint(H[rr * S2_H_STRIDE + kc + 4]);
        af[3] = __float_as_uint(H[(rr + 8) * S2_H_STRIDE + kc + 4]);
        #pragma unroll
        for (int ni = 0; ni < 5; ni++) {
            const int nb = ni * 8 + (lane >> 2);
            const uint32_t b0 =
                __float_as_uint(Ws[(kk + (lane & 3)) * S2_W_STRIDE + nb]);
            const uint32_t b1 =
                __float_as_uint(Ws[(kk + 4 + (lane & 3)) * S2_W_STRIDE + nb]);
            mma_tf32(acc2[ni], af, b0, b1);
        }
    }

    const int row0 = blockRow * 128 + rb2 + (lane >> 2);
    #pragma unroll
    for (int ni = 0; ni < 5; ni++) {
        const int c0 = ni * 8 + 2 * (lane & 3);
        if (row0 < M) {
            float2 v = make_float2(acc2[ni][0], acc2[ni][1]);
            *reinterpret_cast<float2*>(g_h2 + (size_t)row0 * C_DIM + c0) = v;
        }
        if (row0 + 8 < M) {
            float2 v = make_float2(acc2[ni][2], acc2[ni][3]);
            *reinterpret_cast<float2*>(g_h2 + (size_t)(row0 + 8) * C_DIM + c0) = v;
        }
    }
}

// ---------------------------------------------------------------------------
// Row-pointer build: edge_dst is SORTED. rowptr[v] = lower_bound(dst, v).
// ---------------------------------------------------------------------------
__global__ void rowptr_kernel(const int* __restrict__ dst, int N, int E) {
    const int v = blockIdx.x * blockDim.x + threadIdx.x;
    if (v > N) return;
    int lo = 0, hi = E;
    while (lo < hi) {
        const int mid = (lo + hi) >> 1;
        if (__ldg(dst + mid) < v) lo = mid + 1; else hi = mid;
    }
    g_rowptr[v] = lo;
}

// ---------------------------------------------------------------------------
// CSR SPMM: out[v] = sum_{i in [rowptr[v], rowptr[v+1])} val[i] * x[src[i]]
// 320 threads = 32 groups x 10 lanes; group owns one node; lane owns float4.
// 4-edge unroll -> 4 independent LDG.128 gathers in flight per thread.
// No atomics, no output zeroing.
// ---------------------------------------------------------------------------
__device__ __forceinline__ void fma4(float4& a, float v, const float4& x) {
    a.x = fmaf(v, x.x, a.x); a.y = fmaf(v, x.y, a.y);
    a.z = fmaf(v, x.z, a.z); a.w = fmaf(v, x.w, a.w);
}

__global__ __launch_bounds__(320) void spmm_csr_kernel(
    const int* __restrict__ src, const float* __restrict__ val,
    const float* __restrict__ x, float* __restrict__ out, int N) {
    const int tid = threadIdx.x;
    const int node = blockIdx.x * 32 + tid / 10;
    const int lane = tid % 10;
    if (node >= N) return;

    const int start = __ldg(g_rowptr + node);
    const int end   = __ldg(g_rowptr + node + 1);
    const float* xb = x + (size_t)lane * 4;

    float4 a0 = make_float4(0.f, 0.f, 0.f, 0.f);
    float4 a1 = make_float4(0.f, 0.f, 0.f, 0.f);
    float4 a2 = make_float4(0.f, 0.f, 0.f, 0.f);
    float4 a3 = make_float4(0.f, 0.f, 0.f, 0.f);

    int i = start;
    for (; i + 4 <= end; i += 4) {
        const int   s0 = __ldg(src + i);
        const int   s1 = __ldg(src + i + 1);
        const int   s2 = __ldg(src + i + 2);
        const int   s3 = __ldg(src + i + 3);
        const float v0 = __ldg(val + i);
        const float v1 = __ldg(val + i + 1);
        const float v2 = __ldg(val + i + 2);
        const float v3 = __ldg(val + i + 3);
        const float4 x0 = *reinterpret_cast<const float4*>(xb + (size_t)s0 * C_DIM);
        const float4 x1 = *reinterpret_cast<const float4*>(xb + (size_t)s1 * C_DIM);
        const float4 x2 = *reinterpret_cast<const float4*>(xb + (size_t)s2 * C_DIM);
        const float4 x3 = *reinterpret_cast<const float4*>(xb + (size_t)s3 * C_DIM);
        fma4(a0, v0, x0);
        fma4(a1, v1, x1);
        fma4(a2, v2, x2);
        fma4(a3, v3, x3);
    }
    if (i + 2 <= end) {
        const int   s0 = __ldg(src + i);
        const int   s1 = __ldg(src + i + 1);
        const float v0 = __ldg(val + i);
        const float v1 = __ldg(val + i + 1);
        const float4 x0 = *reinterpret_cast<const float4*>(xb + (size_t)s0 * C_DIM);
        const float4 x1 = *reinterpret_cast<const float4*>(xb + (size_t)s1 * C_DIM);
        fma4(a0, v0, x0);
        fma4(a1, v1, x1);
        i += 2;
    }
    if (i < end) {
        const int   s0 = __ldg(src + i);
        const float v0 = __ldg(val + i);
        const float4 x0 = *reinterpret_cast<const float4*>(xb + (size_t)s0 * C_DIM);
        fma4(a0, v0, x0);
    }

    float4 r;
    r.x = (a0.x + a1.x) + (a2.x + a3.x);
    r.y = (a0.y + a1.y) + (a2.y + a3.y);
    r.z = (a0.z + a1.z) + (a2.z + a3.z);
    r.w = (a0.w + a1.w) + (a2.w + a3.w);
    *reinterpret_cast<float4*>(out + (size_t)node * C_DIM + lane * 4) = r;
}

extern "C" void kernel_launch(void* const* d_in, const int* in_sizes, int n_in,
                              void* d_out, int out_size) {
    const float* features = (const float*)d_in[0];
    const float* W1       = (const float*)d_in[1];
    const float* W2       = (const float*)d_in[2];
    const int*   edge_src = (const int*)d_in[3];
    const int*   edge_dst = (const int*)d_in[4];
    const float* edge_val = (const float*)d_in[5];
    float* out = (float*)d_out;

    const int M = in_sizes[0] / IN_DIM;   // 100000
    const int E = in_sizes[3];            // 1600000

    float *p_h2, *p_z1;
    cudaGetSymbolAddress((void**)&p_h2, g_h2);
    cudaGetSymbolAddress((void**)&p_z1, g_z1);

    static bool attr_set = false;
    if (!attr_set) {
        cudaFuncSetAttribute(fused_mlp_kernel,
                             cudaFuncAttributeMaxDynamicSharedMemorySize,
                             FUSED_SMEM_BYTES);
        attr_set = true;
    }

    // 1) h2 = relu(X @ W1) @ W2  (single fused kernel)
    fused_mlp_kernel<<<(M + 127) / 128, 256, FUSED_SMEM_BYTES>>>(
        features, W1, W2, M);

    // 2) CSR row pointers from sorted edge_dst (shared by both propagations)
    rowptr_kernel<<<(M + 257) / 256, 256>>>(edge_dst, M, E);

    // 3) z1 = A @ h2 ; out = A @ z1   (no zeroing, no atomics)
    spmm_csr_kernel<<<(M + 31) / 32, 320>>>(edge_src, edge_val, p_h2, p_z1, M);
    spmm_csr_kernel<<<(M + 31) / 32, 320>>>(edge_src, edge_val, p_z1, out, M);
}